// round 4
// baseline (speedup 1.0000x reference)
#include <cuda_runtime.h>
#include <math.h>

#define B_  8
#define T_  8192
#define F_  64
#define M_  128          // omega rows
#define MM2 256          // feature dim = 2*M
#define D_  64
#define DP_ 65           // D + 1 (normalizer column)
#define KV_CHUNKS 32
#define KV_ROWS (T_ / KV_CHUNKS)   // 256 s-rows per kv block

constexpr float kEPS   = 1e-9f;
constexpr float kSCALE = 0.0625f;  // 1/sqrt(2*128) = 1/16

typedef unsigned long long ull;

// ---------------- packed f32x2 helpers (Blackwell sm_103a) ----------------
__device__ __forceinline__ ull pack2(float a, float b) {
    ull r; asm("mov.b64 %0, {%1,%2};" : "=l"(r) : "f"(a), "f"(b)); return r;
}
__device__ __forceinline__ void unpack2(ull v, float& lo, float& hi) {
    asm("mov.b64 {%0,%1}, %2;" : "=f"(lo), "=f"(hi) : "l"(v));
}
__device__ __forceinline__ ull fma2(ull a, ull b, ull c) {
    ull d; asm("fma.rn.f32x2 %0, %1, %2, %3;" : "=l"(d) : "l"(a), "l"(b), "l"(c)); return d;
}

// ---------------- device scratch (static, allocation-free) ----------------
__device__ float g_phiq[(size_t)B_ * T_ * MM2];                 // 67.1 MB
__device__ float g_phik[(size_t)B_ * T_ * MM2];                 // 67.1 MB
__device__ float g_kvp [(size_t)KV_CHUNKS * B_ * MM2 * DP_];    // 17.0 MB
__device__ float g_kv  [(size_t)B_ * MM2 * DP_];                // 0.53 MB

// ======================= Stage 1: phi features =======================
// grid (T/32, B), block 256, dynamic smem ~78.5 KB.
// xsT:  x transposed [f][row], pad 34 -> row-pair LDS.64 broadcast loads.
// wdup: omega duplicated [f][2m]=[f][2m+1], stride 268 (16B-aligned rows,
//       conflict-free LDS.128 reads -> (w,w) pairs with zero pack MOVs).
// Thread: tx = tid&31 -> m quad, ty = tid>>5 -> rows ty*4..ty*4+3 (2 pairs).
#define XT_S 34
#define WD_S 268
#define PHI_SMEM ((64 * XT_S + 64 * WD_S + 8 * 32 + 32) * 4)

__device__ __forceinline__ void phi_emit(float* __restrict__ phi, int b, int t0,
                                         int r, int tx, float s,
                                         float a0, float a1, float a2v, float a3)
{
    float4 p1, p2;
    p1.x = (__expf( a0 - s) + kEPS) * kSCALE;
    p1.y = (__expf( a1 - s) + kEPS) * kSCALE;
    p1.z = (__expf( a2v - s) + kEPS) * kSCALE;
    p1.w = (__expf( a3 - s) + kEPS) * kSCALE;
    p2.x = (__expf(-a0 - s) + kEPS) * kSCALE;
    p2.y = (__expf(-a1 - s) + kEPS) * kSCALE;
    p2.z = (__expf(-a2v - s) + kEPS) * kSCALE;
    p2.w = (__expf(-a3 - s) + kEPS) * kSCALE;
    float* dst = phi + ((size_t)b * T_ + t0 + r) * MM2 + tx * 4;
    *reinterpret_cast<float4*>(dst)      = p1;
    *reinterpret_cast<float4*>(dst + M_) = p2;
}

__global__ void __launch_bounds__(256) phi_kernel(const float* __restrict__ x,
                                                  const float* __restrict__ omega,
                                                  int which)
{
    extern __shared__ float sm[];
    float* xsT  = sm;                      // [64][34]
    float* wdup = sm + 64 * XT_S;          // [64][268]
    float* ssp  = wdup + 64 * WD_S;        // [8][32]
    float* ss   = ssp + 256;               // [32]

    float* phi = which ? g_phik : g_phiq;
    const int b   = blockIdx.y;
    const int t0  = blockIdx.x * 32;
    const int tid = threadIdx.x;

    // load x tile transposed (coalesced global float4)
    {
        const float4* xg = reinterpret_cast<const float4*>(x + ((size_t)b * T_ + t0) * F_);
        #pragma unroll
        for (int it = 0; it < 2; it++) {
            int idx = tid + 256 * it;            // 0..511
            int r = idx >> 4, f4 = (idx & 15) << 2;
            float4 v = xg[idx];
            xsT[(f4 + 0) * XT_S + r] = v.x;
            xsT[(f4 + 1) * XT_S + r] = v.y;
            xsT[(f4 + 2) * XT_S + r] = v.z;
            xsT[(f4 + 3) * XT_S + r] = v.w;
        }
    }
    // load omega duplicated: wdup[f][2m] = wdup[f][2m+1] = omega[m][f]
    #pragma unroll
    for (int i = 0; i < 32; i++) {
        int idx = tid + 256 * i;                 // 8192 floats, omega[m][f]
        float wv = omega[idx];
        int m = idx >> 6, f = idx & 63;
        wdup[f * WD_S + 2 * m]     = wv;
        wdup[f * WD_S + 2 * m + 1] = wv;
    }
    __syncthreads();

    // ss[r] = 0.5 * sum_f x[r][f]^2 (two-step, conflict-free)
    {
        int r = tid & 31, fg = tid >> 5;
        float p = 0.f;
        #pragma unroll
        for (int k2 = 0; k2 < 8; k2++) { float v = xsT[(fg * 8 + k2) * XT_S + r]; p += v * v; }
        ssp[fg * 32 + r] = p;
    }
    __syncthreads();
    if (tid < 32) {
        float p = 0.f;
        #pragma unroll
        for (int k2 = 0; k2 < 8; k2++) p += ssp[k2 * 32 + tid];
        ss[tid] = 0.5f * p;
    }
    __syncthreads();

    const int tx = tid & 31;
    const int ty = tid >> 5;

    ull a2[2][4];
    #pragma unroll
    for (int jp = 0; jp < 2; jp++)
        #pragma unroll
        for (int c = 0; c < 4; c++) a2[jp][c] = 0ULL;

    // xw GEMM: per f: 2 LDS.64 (row pairs, broadcast) + 2 LDS.128 (w dup) + 8 FFMA2
    #pragma unroll 16
    for (int f = 0; f < 64; f++) {
        ull xp0 = *reinterpret_cast<const ull*>(&xsT[f * XT_S + ty * 4]);
        ull xp1 = *reinterpret_cast<const ull*>(&xsT[f * XT_S + ty * 4 + 2]);
        ulonglong2 wa = *reinterpret_cast<const ulonglong2*>(&wdup[f * WD_S + 8 * tx]);
        ulonglong2 wb = *reinterpret_cast<const ulonglong2*>(&wdup[f * WD_S + 8 * tx + 4]);
        a2[0][0] = fma2(xp0, wa.x, a2[0][0]);
        a2[0][1] = fma2(xp0, wa.y, a2[0][1]);
        a2[0][2] = fma2(xp0, wb.x, a2[0][2]);
        a2[0][3] = fma2(xp0, wb.y, a2[0][3]);
        a2[1][0] = fma2(xp1, wa.x, a2[1][0]);
        a2[1][1] = fma2(xp1, wa.y, a2[1][1]);
        a2[1][2] = fma2(xp1, wb.x, a2[1][2]);
        a2[1][3] = fma2(xp1, wb.y, a2[1][3]);
    }

    #pragma unroll
    for (int jp = 0; jp < 2; jp++) {
        float e0, e1, e2, e3, o0, o1, o2, o3;
        unpack2(a2[jp][0], e0, o0);
        unpack2(a2[jp][1], e1, o1);
        unpack2(a2[jp][2], e2, o2);
        unpack2(a2[jp][3], e3, o3);
        int r = ty * 4 + jp * 2;
        phi_emit(phi, b, t0, r,     tx, ss[r],     e0, e1, e2, e3);
        phi_emit(phi, b, t0, r + 1, tx, ss[r + 1], o0, o1, o2, o3);
    }
}

// ======================= Stage 2: kv partials =======================
// grid (KV_CHUNKS, B), block 256. Thread owns feature m = tid; packed accs.
__global__ void __launch_bounds__(256) kv_kernel(const float* __restrict__ value)
{
    __shared__ float vs[16][68];   // staged V rows; broadcast reads

    const int b   = blockIdx.y;
    const int cx  = blockIdx.x;
    const int s0  = cx * KV_ROWS;
    const int tid = threadIdx.x;

    ull acc2[32];
    float accn = 0.f;
    #pragma unroll
    for (int i = 0; i < 32; i++) acc2[i] = 0ULL;

    const float*  phik = g_phik + ((size_t)b * T_ + s0) * MM2 + tid;   // coalesced
    const float4* vg   = reinterpret_cast<const float4*>(value + ((size_t)b * T_ + s0) * D_);
    const int lr = tid >> 4, lc = tid & 15;

    for (int sb = 0; sb < KV_ROWS; sb += 16) {
        __syncthreads();
        {   // stage 16 V rows (16x64 floats = 256 float4, one per thread)
            float4 v = vg[(sb + lr) * 16 + lc];
            *reinterpret_cast<float4*>(&vs[lr][lc * 4]) = v;
        }
        __syncthreads();
        #pragma unroll
        for (int j = 0; j < 16; j++) {
            float ph = phik[(size_t)(sb + j) * MM2];
            ull ph2 = pack2(ph, ph);
            #pragma unroll
            for (int q = 0; q < 16; q++) {
                ulonglong2 vv = *reinterpret_cast<const ulonglong2*>(&vs[j][q * 4]);
                acc2[2 * q]     = fma2(ph2, vv.x, acc2[2 * q]);
                acc2[2 * q + 1] = fma2(ph2, vv.y, acc2[2 * q + 1]);
            }
            accn += ph;   // ones column: normalizer = sum(phi)
        }
    }

    float* dst = g_kvp + (((size_t)cx * B_ + b) * MM2 + tid) * DP_;
    #pragma unroll
    for (int i = 0; i < 32; i++) {
        float lo, hi;
        unpack2(acc2[i], lo, hi);
        dst[2 * i]     = lo;
        dst[2 * i + 1] = hi;
    }
    dst[64] = accn;
}

// ======================= Stage 2b: reduce partials (float4) =======================
#define KV_N4 (B_ * MM2 * DP_ / 4)   // 33280

__global__ void __launch_bounds__(256) reduce_kv()
{
    int i = blockIdx.x * blockDim.x + threadIdx.x;
    if (i < KV_N4) {
        const float4* src = reinterpret_cast<const float4*>(g_kvp);
        float4 s = make_float4(0.f, 0.f, 0.f, 0.f);
        #pragma unroll
        for (int c = 0; c < KV_CHUNKS; c++) {
            float4 v = src[(size_t)c * KV_N4 + i];
            s.x += v.x; s.y += v.y; s.z += v.z; s.w += v.w;
        }
        reinterpret_cast<float4*>(g_kv)[i] = s;
    }
}

// ======================= Stage 3: qkv + normalize =======================
// grid (T/64, B), block 256, dynamic smem 136 KB.
// Thread (tt = tid>>2 row, p = tid&3 owns 16 cols as 8 packed accs).
#define QKV_SMEM ((256 * 68 + 64 * 260 + 64) * 4)

__global__ void __launch_bounds__(256) qkv_kernel(float* __restrict__ out)
{
    extern __shared__ float sm[];
    float* kvs  = sm;               // [256][68] padded
    float* phis = sm + 256 * 68;    // [64][260] padded
    float* norm = phis + 64 * 260;  // [64]

    const int b   = blockIdx.y;
    const int t0  = blockIdx.x * 64;
    const int tid = threadIdx.x;

    // load kv matrix for this batch
    const float* kvg = g_kv + (size_t)b * MM2 * DP_;
    for (int i = tid; i < MM2 * DP_; i += 256) {
        int r = i / DP_;
        int d = i - r * DP_;
        kvs[r * 68 + d] = kvg[i];
    }
    // load phi_q tile (64 x 256), coalesced float4
    const float4* pg = reinterpret_cast<const float4*>(g_phiq + ((size_t)b * T_ + t0) * MM2);
    #pragma unroll
    for (int i = 0; i < 16; i++) {
        int idx = tid + 256 * i;           // 4096 float4
        int r = idx >> 6, c4 = idx & 63;
        *reinterpret_cast<float4*>(&phis[r * 260 + c4 * 4]) = pg[idx];
    }
    __syncthreads();

    const int tt  = tid >> 2;
    const int p   = tid & 3;
    const int dof = p * 16;
    const float* ph = &phis[tt * 260];

    ull a2[8];
    #pragma unroll
    for (int i = 0; i < 8; i++) a2[i] = 0ULL;
    float anorm = 0.f;

    #pragma unroll 8
    for (int m = 0; m < MM2; m++) {
        float f = ph[m];
        ull f2 = pack2(f, f);
        const float* kr = &kvs[m * 68 + dof];
        ulonglong2 k0 = *reinterpret_cast<const ulonglong2*>(kr);
        ulonglong2 k1 = *reinterpret_cast<const ulonglong2*>(kr + 4);
        ulonglong2 k2 = *reinterpret_cast<const ulonglong2*>(kr + 8);
        ulonglong2 k3 = *reinterpret_cast<const ulonglong2*>(kr + 12);
        a2[0] = fma2(f2, k0.x, a2[0]);
        a2[1] = fma2(f2, k0.y, a2[1]);
        a2[2] = fma2(f2, k1.x, a2[2]);
        a2[3] = fma2(f2, k1.y, a2[3]);
        a2[4] = fma2(f2, k2.x, a2[4]);
        a2[5] = fma2(f2, k2.y, a2[5]);
        a2[6] = fma2(f2, k3.x, a2[6]);
        a2[7] = fma2(f2, k3.y, a2[7]);
        if (p == 3) anorm += f * kvs[m * 68 + 64];
    }

    if (p == 3) norm[tt] = anorm;
    __syncthreads();

    float inv = 1.0f / norm[tt];
    float lo0, hi0, lo1, hi1;
    float4 og0, og1, og2, og3;
    unpack2(a2[0], lo0, hi0); unpack2(a2[1], lo1, hi1);
    og0 = make_float4(lo0 * inv, hi0 * inv, lo1 * inv, hi1 * inv);
    unpack2(a2[2], lo0, hi0); unpack2(a2[3], lo1, hi1);
    og1 = make_float4(lo0 * inv, hi0 * inv, lo1 * inv, hi1 * inv);
    unpack2(a2[4], lo0, hi0); unpack2(a2[5], lo1, hi1);
    og2 = make_float4(lo0 * inv, hi0 * inv, lo1 * inv, hi1 * inv);
    unpack2(a2[6], lo0, hi0); unpack2(a2[7], lo1, hi1);
    og3 = make_float4(lo0 * inv, hi0 * inv, lo1 * inv, hi1 * inv);

    float4* og = reinterpret_cast<float4*>(out + ((size_t)b * T_ + t0 + tt) * D_ + dof);
    og[0] = og0; og[1] = og1; og[2] = og2; og[3] = og3;
}

// ======================= launch =======================
extern "C" void kernel_launch(void* const* d_in, const int* in_sizes, int n_in,
                              void* d_out, int out_size)
{
    const float* query = (const float*)d_in[0];
    const float* value = (const float*)d_in[1];
    const float* key   = (const float*)d_in[2];
    const float* omega = (const float*)d_in[3];
    float* out = (float*)d_out;

    cudaFuncSetAttribute(phi_kernel, cudaFuncAttributeMaxDynamicSharedMemorySize, PHI_SMEM);
    cudaFuncSetAttribute(qkv_kernel, cudaFuncAttributeMaxDynamicSharedMemorySize, QKV_SMEM);

    dim3 gphi(T_ / 32, B_);
    phi_kernel<<<gphi, 256, PHI_SMEM>>>(key,   omega, 1);
    phi_kernel<<<gphi, 256, PHI_SMEM>>>(query, omega, 0);

    dim3 gkv(KV_CHUNKS, B_);
    kv_kernel<<<gkv, 256>>>(value);
    reduce_kv<<<(KV_N4 + 255) / 256, 256>>>();

    dim3 gq(T_ / 64, B_);
    qkv_kernel<<<gq, 256, QKV_SMEM>>>(out);
}

// round 5
// speedup vs baseline: 1.2760x; 1.2760x over previous
#include <cuda_runtime.h>
#include <math.h>

#define B_  8
#define T_  8192
#define F_  64
#define M_  128          // omega rows
#define MM2 256          // feature dim = 2*M
#define D_  64
#define DP_ 65           // D + 1 (normalizer column)

#define KV_CH    37      // kv chunks -> grid 37*8 = 296 = exactly 2 waves of 148
#define KV_ROWS  224     // rows per chunk (37*224 = 8288 >= 8192, tail masked)

constexpr float kEPS   = 1e-9f;
constexpr float kSCALE = 0.0625f;  // 1/sqrt(2*128) = 1/16

// ---------------- device scratch (static, allocation-free) ----------------
__device__ float g_kvp[(size_t)KV_CH * B_ * MM2 * DP_];    // 19.7 MB
__device__ float g_kv [(size_t)B_ * MM2 * DP_];            // 0.53 MB

// ======================= Stage 1: kv_fused (phi_k + kv) =======================
// grid (KV_CH, B), block 256. Per 16-row step: build phi_k tile in smem, then
// accumulate 65 per-feature sums. Thread owns feature m = tid in accumulate.
#define KVF_WT   0
#define KVF_XS   (64 * 132)
#define KVF_VS   (KVF_XS + 16 * 68)
#define KVF_PHI  (KVF_VS + 16 * 68)
#define KVF_SS   (KVF_PHI + 16 * 260)
#define KVF_SMEM ((KVF_SS + 16) * 4)

__global__ void __launch_bounds__(256) kv_fused(const float* __restrict__ key,
                                                const float* __restrict__ value,
                                                const float* __restrict__ omega)
{
    extern __shared__ float sm[];
    float* wT   = sm + KVF_WT;
    float* xs   = sm + KVF_XS;
    float* vs   = sm + KVF_VS;
    float* phis = sm + KVF_PHI;
    float* ss   = sm + KVF_SS;

    const int b   = blockIdx.y;
    const int cx  = blockIdx.x;
    const int s0  = cx * KV_ROWS;
    const int tid = threadIdx.x;

    // load omega transposed: wT[f][m] (one-time, 4-way write conflict ok)
    #pragma unroll
    for (int i = 0; i < 32; i++) {
        int idx = tid + 256 * i;               // 8192 floats, omega[m][f]
        wT[(idx & 63) * 132 + (idx >> 6)] = omega[idx];
    }

    float acc[DP_];
    #pragma unroll
    for (int d = 0; d < DP_; d++) acc[d] = 0.f;

    const int tx = tid & 31;   // m quad (4*tx of 128)
    const int ty = tid >> 5;   // row pair (2*ty, 2*ty+1)
    const int lr = tid >> 4;   // staging row 0..15
    const int lc = tid & 15;   // staging float4 col

    for (int sb = 0; sb < KV_ROWS; sb += 16) {
        const int sg = s0 + sb;                // global row base of this step
        __syncthreads();                       // prev accumulate done (vs/phis free)

        // ---- stage 16 key rows + 16 value rows; ss via half-warp shfl ----
        {
            const int r = sg + lr;
            float4 xv = make_float4(0.f, 0.f, 0.f, 0.f);
            float4 vv = make_float4(0.f, 0.f, 0.f, 0.f);
            if (r < T_) {
                xv = *reinterpret_cast<const float4*>(key   + ((size_t)b * T_ + r) * F_ + lc * 4);
                vv = *reinterpret_cast<const float4*>(value + ((size_t)b * T_ + r) * D_ + lc * 4);
            }
            *reinterpret_cast<float4*>(&xs[lr * 68 + lc * 4]) = xv;
            *reinterpret_cast<float4*>(&vs[lr * 68 + lc * 4]) = vv;
            float p = xv.x * xv.x + xv.y * xv.y + xv.z * xv.z + xv.w * xv.w;
            p += __shfl_xor_sync(0xffffffffu, p, 8);
            p += __shfl_xor_sync(0xffffffffu, p, 4);
            p += __shfl_xor_sync(0xffffffffu, p, 2);
            p += __shfl_xor_sync(0xffffffffu, p, 1);
            if (lc == 0) ss[lr] = 0.5f * p;
        }
        __syncthreads();

        // ---- phi GEMM: 2 rows x 4 m per thread ----
        {
            float a[2][4];
            #pragma unroll
            for (int jp = 0; jp < 2; jp++)
                #pragma unroll
                for (int c = 0; c < 4; c++) a[jp][c] = 0.f;

            #pragma unroll
            for (int f0 = 0; f0 < 64; f0 += 4) {
                float4 w0 = *reinterpret_cast<const float4*>(&wT[(f0 + 0) * 132 + tx * 4]);
                float4 w1 = *reinterpret_cast<const float4*>(&wT[(f0 + 1) * 132 + tx * 4]);
                float4 w2 = *reinterpret_cast<const float4*>(&wT[(f0 + 2) * 132 + tx * 4]);
                float4 w3 = *reinterpret_cast<const float4*>(&wT[(f0 + 3) * 132 + tx * 4]);
                #pragma unroll
                for (int jp = 0; jp < 2; jp++) {
                    float4 xv = *reinterpret_cast<const float4*>(&xs[(ty * 2 + jp) * 68 + f0]);
                    a[jp][0] += xv.x * w0.x + xv.y * w1.x + xv.z * w2.x + xv.w * w3.x;
                    a[jp][1] += xv.x * w0.y + xv.y * w1.y + xv.z * w2.y + xv.w * w3.y;
                    a[jp][2] += xv.x * w0.z + xv.y * w1.z + xv.z * w2.z + xv.w * w3.z;
                    a[jp][3] += xv.x * w0.w + xv.y * w1.w + xv.z * w2.w + xv.w * w3.w;
                }
            }
            // exp + masked scale, store to phis
            #pragma unroll
            for (int jp = 0; jp < 2; jp++) {
                int r = ty * 2 + jp;
                float s  = ss[r];
                float sc = (sg + r < T_) ? kSCALE : 0.f;
                float4 p1, p2;
                p1.x = (__expf( a[jp][0] - s) + kEPS) * sc;
                p1.y = (__expf( a[jp][1] - s) + kEPS) * sc;
                p1.z = (__expf( a[jp][2] - s) + kEPS) * sc;
                p1.w = (__expf( a[jp][3] - s) + kEPS) * sc;
                p2.x = (__expf(-a[jp][0] - s) + kEPS) * sc;
                p2.y = (__expf(-a[jp][1] - s) + kEPS) * sc;
                p2.z = (__expf(-a[jp][2] - s) + kEPS) * sc;
                p2.w = (__expf(-a[jp][3] - s) + kEPS) * sc;
                *reinterpret_cast<float4*>(&phis[r * 260 + tx * 4])       = p1;
                *reinterpret_cast<float4*>(&phis[r * 260 + 128 + tx * 4]) = p2;
            }
        }
        __syncthreads();

        // ---- accumulate: thread owns feature m = tid ----
        #pragma unroll
        for (int j = 0; j < 16; j++) {
            float ph = phis[j * 260 + tid];
            #pragma unroll
            for (int q = 0; q < 16; q++) {
                float4 vv = *reinterpret_cast<const float4*>(&vs[j * 68 + q * 4]);
                acc[q * 4 + 0] += ph * vv.x;
                acc[q * 4 + 1] += ph * vv.y;
                acc[q * 4 + 2] += ph * vv.z;
                acc[q * 4 + 3] += ph * vv.w;
            }
            acc[64] += ph;   // normalizer column
        }
    }

    float* dst = g_kvp + (((size_t)cx * B_ + b) * MM2 + tid) * DP_;
    #pragma unroll
    for (int d = 0; d < DP_; d++) dst[d] = acc[d];
}

// ======================= Stage 2: reduce partials (float4) =======================
#define KV_N4 (B_ * MM2 * DP_ / 4)   // 33280

__global__ void __launch_bounds__(256) reduce_kv()
{
    int i = blockIdx.x * blockDim.x + threadIdx.x;
    if (i < KV_N4) {
        const float4* src = reinterpret_cast<const float4*>(g_kvp);
        float4 s = make_float4(0.f, 0.f, 0.f, 0.f);
        #pragma unroll
        for (int c = 0; c < KV_CH; c++) {
            float4 v = src[(size_t)c * KV_N4 + i];
            s.x += v.x; s.y += v.y; s.z += v.z; s.w += v.w;
        }
        reinterpret_cast<float4*>(g_kv)[i] = s;
    }
}

// ======================= Stage 3: qkv_fused (phi_q + qkv + normalize) =======================
#define QF_KVS  0
#define QF_WT   (256 * 68)
#define QF_XS   (QF_WT + 64 * 132)
#define QF_PHI  (QF_XS + 64 * 68)
#define QF_SS   (QF_PHI + 64 * 260)
#define QF_NRM  (QF_SS + 64)
#define QF_SMEM ((QF_NRM + 64) * 4)

__global__ void __launch_bounds__(256) qkv_fused(const float* __restrict__ query,
                                                 const float* __restrict__ omega,
                                                 float* __restrict__ out)
{
    extern __shared__ float sm[];
    float* kvs  = sm + QF_KVS;     // [256][68]
    float* wT   = sm + QF_WT;      // [64][132]
    float* xs   = sm + QF_XS;      // [64][68]
    float* phis = sm + QF_PHI;     // [64][260]
    float* ss   = sm + QF_SS;      // [64]
    float* norm = sm + QF_NRM;     // [64]

    const int b   = blockIdx.y;
    const int t0  = blockIdx.x * 64;
    const int tid = threadIdx.x;

    // ---- loads: kv matrix, omega^T, query tile ----
    {
        const float* kvg = g_kv + (size_t)b * MM2 * DP_;
        for (int i = tid; i < MM2 * DP_; i += 256) {
            int r = i / DP_;
            int d = i - r * DP_;
            kvs[r * 68 + d] = kvg[i];
        }
        #pragma unroll
        for (int i = 0; i < 32; i++) {
            int idx = tid + 256 * i;
            wT[(idx & 63) * 132 + (idx >> 6)] = omega[idx];
        }
        const float4* xg = reinterpret_cast<const float4*>(query + ((size_t)b * T_ + t0) * F_);
        #pragma unroll
        for (int i = 0; i < 4; i++) {
            int idx = tid + 256 * i;           // 1024 float4
            int r = idx >> 4, c4 = idx & 15;
            *reinterpret_cast<float4*>(&xs[r * 68 + c4 * 4]) = xg[idx];
        }
    }
    __syncthreads();

    // ---- ss[r] = 0.5 * ||x_r||^2 ----
    if (tid < 64) {
        float p = 0.f;
        #pragma unroll
        for (int f = 0; f < 64; f++) { float v = xs[tid * 68 + f]; p += v * v; }
        ss[tid] = 0.5f * p;
    }
    __syncthreads();

    // ---- phase A: phi_q GEMM, 8 rows x 4 m per thread ----
    {
        const int tx = tid & 31;
        const int ty = tid >> 5;
        float a[8][4];
        #pragma unroll
        for (int j = 0; j < 8; j++)
            #pragma unroll
            for (int c = 0; c < 4; c++) a[j][c] = 0.f;

        #pragma unroll 8
        for (int f0 = 0; f0 < 64; f0 += 4) {
            float4 w0 = *reinterpret_cast<const float4*>(&wT[(f0 + 0) * 132 + tx * 4]);
            float4 w1 = *reinterpret_cast<const float4*>(&wT[(f0 + 1) * 132 + tx * 4]);
            float4 w2 = *reinterpret_cast<const float4*>(&wT[(f0 + 2) * 132 + tx * 4]);
            float4 w3 = *reinterpret_cast<const float4*>(&wT[(f0 + 3) * 132 + tx * 4]);
            #pragma unroll
            for (int j = 0; j < 8; j++) {
                float4 xv = *reinterpret_cast<const float4*>(&xs[(ty * 8 + j) * 68 + f0]);
                a[j][0] += xv.x * w0.x + xv.y * w1.x + xv.z * w2.x + xv.w * w3.x;
                a[j][1] += xv.x * w0.y + xv.y * w1.y + xv.z * w2.y + xv.w * w3.y;
                a[j][2] += xv.x * w0.z + xv.y * w1.z + xv.z * w2.z + xv.w * w3.z;
                a[j][3] += xv.x * w0.w + xv.y * w1.w + xv.z * w2.w + xv.w * w3.w;
            }
        }
        #pragma unroll
        for (int j = 0; j < 8; j++) {
            int r = ty * 8 + j;
            float s = ss[r];
            float4 p1, p2;
            p1.x = (__expf( a[j][0] - s) + kEPS) * kSCALE;
            p1.y = (__expf( a[j][1] - s) + kEPS) * kSCALE;
            p1.z = (__expf( a[j][2] - s) + kEPS) * kSCALE;
            p1.w = (__expf( a[j][3] - s) + kEPS) * kSCALE;
            p2.x = (__expf(-a[j][0] - s) + kEPS) * kSCALE;
            p2.y = (__expf(-a[j][1] - s) + kEPS) * kSCALE;
            p2.z = (__expf(-a[j][2] - s) + kEPS) * kSCALE;
            p2.w = (__expf(-a[j][3] - s) + kEPS) * kSCALE;
            *reinterpret_cast<float4*>(&phis[r * 260 + tx * 4])       = p1;
            *reinterpret_cast<float4*>(&phis[r * 260 + 128 + tx * 4]) = p2;
        }
    }
    __syncthreads();

    // ---- phase B: out = phi_q @ kv, normalized ----
    const int tt  = tid >> 2;
    const int p   = tid & 3;
    const int dof = p * 16;
    const float* ph = &phis[tt * 260];

    float4 a0 = make_float4(0.f, 0.f, 0.f, 0.f), a1 = a0, a2 = a0, a3 = a0;
    float anorm = 0.f;

    #pragma unroll 8
    for (int m = 0; m < MM2; m++) {
        float f = ph[m];
        const float* kr = &kvs[m * 68 + dof];
        float4 k0 = *reinterpret_cast<const float4*>(kr);
        float4 k1 = *reinterpret_cast<const float4*>(kr + 4);
        float4 k2 = *reinterpret_cast<const float4*>(kr + 8);
        float4 k3 = *reinterpret_cast<const float4*>(kr + 12);
        a0.x += f * k0.x; a0.y += f * k0.y; a0.z += f * k0.z; a0.w += f * k0.w;
        a1.x += f * k1.x; a1.y += f * k1.y; a1.z += f * k1.z; a1.w += f * k1.w;
        a2.x += f * k2.x; a2.y += f * k2.y; a2.z += f * k2.z; a2.w += f * k2.w;
        a3.x += f * k3.x; a3.y += f * k3.y; a3.z += f * k3.z; a3.w += f * k3.w;
        if (p == 3) anorm += f * kvs[m * 68 + 64];
    }

    if (p == 3) norm[tt] = anorm;
    __syncthreads();

    float inv = 1.0f / norm[tt];
    a0.x *= inv; a0.y *= inv; a0.z *= inv; a0.w *= inv;
    a1.x *= inv; a1.y *= inv; a1.z *= inv; a1.w *= inv;
    a2.x *= inv; a2.y *= inv; a2.z *= inv; a2.w *= inv;
    a3.x *= inv; a3.y *= inv; a3.z *= inv; a3.w *= inv;

    float4* og = reinterpret_cast<float4*>(out + ((size_t)b * T_ + t0 + tt) * D_ + dof);
    og[0] = a0; og[1] = a1; og[2] = a2; og[3] = a3;
}

// ======================= launch =======================
extern "C" void kernel_launch(void* const* d_in, const int* in_sizes, int n_in,
                              void* d_out, int out_size)
{
    const float* query = (const float*)d_in[0];
    const float* value = (const float*)d_in[1];
    const float* key   = (const float*)d_in[2];
    const float* omega = (const float*)d_in[3];
    float* out = (float*)d_out;

    cudaFuncSetAttribute(kv_fused,  cudaFuncAttributeMaxDynamicSharedMemorySize, KVF_SMEM);
    cudaFuncSetAttribute(qkv_fused, cudaFuncAttributeMaxDynamicSharedMemorySize, QF_SMEM);

    dim3 gkv(KV_CH, B_);
    kv_fused<<<gkv, 256, KVF_SMEM>>>(key, value, omega);
    reduce_kv<<<(KV_N4 + 255) / 256, 256>>>();

    dim3 gq(T_ / 64, B_);
    qkv_fused<<<gq, 256, QF_SMEM>>>(query, omega, out);
}